// round 1
// baseline (speedup 1.0000x reference)
#include <cuda_runtime.h>
#include <cstddef>

#define D 128
#define EPS_BN 1e-5f
#define MAX_NODES 100000

// ---------------- scratch (allocation-free rule: __device__ globals) --------
__device__ float g_hA[(size_t)MAX_NODES * D];   // 51.2 MB
__device__ float g_hB[(size_t)MAX_NODES * D];   // 51.2 MB
__device__ float g_stats[2 * D];                // col sums / sumsqs
__device__ float g_scale[D];                    // BN fused scale
__device__ float g_shift[D];                    // BN fused shift

// ---------------- zero ------------------------------------------------------
__global__ void zero_kernel(float* __restrict__ p, int n) {
    int i = blockIdx.x * blockDim.x + threadIdx.x;
    int stride = gridDim.x * blockDim.x;
    for (; i < n; i += stride) p[i] = 0.0f;
}

// ---------------- GEMM: Y = act(X) @ W + b ---------------------------------
// act(v) = relu(v*scale[c] + shift[c]) when use_bn, else identity.
// Block: 256 threads, 64 rows x 128 cols tile, K-tiles of 32.
// Each thread: 8 rows x 4 cols micro-tile.
__global__ __launch_bounds__(256) void gemm_kernel(
    const float* __restrict__ X, const float* __restrict__ W,
    const float* __restrict__ bias,
    const float* __restrict__ bn_scale, const float* __restrict__ bn_shift,
    float* __restrict__ Y, int nrows, int use_bn)
{
    __shared__ float xs[64][33];
    __shared__ __align__(16) float ws[32][128];

    int t  = threadIdx.x;
    int tx = t & 31;        // col group: cols tx*4 .. tx*4+3
    int ty = t >> 5;        // row group: rows ty*8 .. ty*8+7
    int row0 = blockIdx.x * 64;

    float acc[8][4];
#pragma unroll
    for (int i = 0; i < 8; i++)
#pragma unroll
        for (int j = 0; j < 4; j++) acc[i][j] = 0.0f;

    for (int k0 = 0; k0 < D; k0 += 32) {
        // load W tile (32 x 128) via float4: 1024 float4, 4 per thread
#pragma unroll
        for (int i = 0; i < 4; i++) {
            int fi = t + i * 256;           // float4 index
            int k  = fi >> 5;               // 0..31
            int c4 = fi & 31;               // 0..31
            *(float4*)&ws[k][c4 * 4] =
                *(const float4*)&W[(size_t)(k0 + k) * D + c4 * 4];
        }
        // load X tile (64 x 32), fused BN+ReLU on the fly
#pragma unroll
        for (int i = 0; i < 8; i++) {
            int fi = t + i * 256;           // element index, 2048 total
            int r  = fi >> 5;               // 0..63
            int k  = fi & 31;               // 0..31
            int row = row0 + r;
            float v = 0.0f;
            if (row < nrows) {
                v = X[(size_t)row * D + k0 + k];
                if (use_bn)
                    v = fmaxf(v * bn_scale[k0 + k] + bn_shift[k0 + k], 0.0f);
            }
            xs[r][k] = v;
        }
        __syncthreads();

#pragma unroll
        for (int k = 0; k < 32; k++) {
            float4 wv = *(const float4*)&ws[k][tx * 4];
#pragma unroll
            for (int i = 0; i < 8; i++) {
                float xv = xs[ty * 8 + i][k];
                acc[i][0] += xv * wv.x;
                acc[i][1] += xv * wv.y;
                acc[i][2] += xv * wv.z;
                acc[i][3] += xv * wv.w;
            }
        }
        __syncthreads();
    }

    float4 bv = *(const float4*)&bias[tx * 4];
#pragma unroll
    for (int i = 0; i < 8; i++) {
        int row = row0 + ty * 8 + i;
        if (row < nrows) {
            float4 o;
            o.x = acc[i][0] + bv.x;
            o.y = acc[i][1] + bv.y;
            o.z = acc[i][2] + bv.z;
            o.w = acc[i][3] + bv.w;
            *(float4*)&Y[(size_t)row * D + tx * 4] = o;
        }
    }
}

// ---------------- SpMM: out[r] += w_e * H[col_e]  (COO, warp per edge) -----
__global__ __launch_bounds__(256) void spmm_kernel(
    const int* __restrict__ rows, const int* __restrict__ cols,
    const float* __restrict__ w, const float* __restrict__ H,
    float* __restrict__ out, int nedges)
{
    int e = (int)((blockIdx.x * 256u + threadIdx.x) >> 5);
    if (e >= nedges) return;
    int lane = threadIdx.x & 31;

    int   r  = __ldg(&rows[e]);
    int   c  = __ldg(&cols[e]);
    float wt = __ldg(&w[e]);

    float4 v = *(const float4*)&H[(size_t)c * D + lane * 4];
    float* dst = &out[(size_t)r * D + lane * 4];
    asm volatile("red.global.add.v4.f32 [%0], {%1,%2,%3,%4};"
                 :: "l"(dst), "f"(v.x * wt), "f"(v.y * wt),
                    "f"(v.z * wt), "f"(v.w * wt)
                 : "memory");
}

// ---------------- BN column stats -------------------------------------------
__global__ void colstats_kernel(const float* __restrict__ H, int nrows) {
    int c = threadIdx.x;   // 128 threads = 128 columns
    float s = 0.0f, q = 0.0f;
    for (int r = blockIdx.x; r < nrows; r += gridDim.x) {
        float v = H[(size_t)r * D + c];
        s += v;
        q += v * v;
    }
    atomicAdd(&g_stats[c], s);
    atomicAdd(&g_stats[D + c], q);
}

__global__ void bnfinal_kernel(const float* __restrict__ g,
                               const float* __restrict__ be, float inv_n) {
    int c = threadIdx.x;
    float m   = g_stats[c] * inv_n;
    float var = g_stats[D + c] * inv_n - m * m;
    float rs  = rsqrtf(var + EPS_BN);
    float sc  = g[c] * rs;
    g_scale[c] = sc;
    g_shift[c] = be[c] - m * sc;
}

// ---------------- launch -----------------------------------------------------
extern "C" void kernel_launch(void* const* d_in, const int* in_sizes, int n_in,
                              void* d_out, int out_size)
{
    const float* x   = (const float*)d_in[0];
    const float* ew  = (const float*)d_in[1];
    const float* W0  = (const float*)d_in[2];
    const float* b0  = (const float*)d_in[3];
    const float* g0  = (const float*)d_in[4];
    const float* be0 = (const float*)d_in[5];
    const float* W1  = (const float*)d_in[6];
    const float* b1  = (const float*)d_in[7];
    const float* g1  = (const float*)d_in[8];
    const float* be1 = (const float*)d_in[9];
    const float* W2  = (const float*)d_in[10];
    const float* b2  = (const float*)d_in[11];
    const int*   row = (const int*)d_in[12];
    const int*   col = (const int*)d_in[13];
    float* out = (float*)d_out;

    int nrows  = in_sizes[0] / D;
    int nedges = in_sizes[1];
    float inv_n = 1.0f / (float)nrows;

    float *hA, *hB, *stats, *scale, *shift;
    cudaGetSymbolAddress((void**)&hA, g_hA);
    cudaGetSymbolAddress((void**)&hB, g_hB);
    cudaGetSymbolAddress((void**)&stats, g_stats);
    cudaGetSymbolAddress((void**)&scale, g_scale);
    cudaGetSymbolAddress((void**)&shift, g_shift);

    dim3 gemm_grid((nrows + 63) / 64);
    int spmm_blocks = (nedges + 7) / 8;     // warp per edge, 8 warps/block
    int nelem = nrows * D;

    // ---- layer 1: h = relu(bn(spmm(x @ W0 + b0))) ----
    gemm_kernel<<<gemm_grid, 256>>>(x, W0, b0, nullptr, nullptr, hA, nrows, 0);
    zero_kernel<<<1024, 256>>>(hB, nelem);
    spmm_kernel<<<spmm_blocks, 256>>>(row, col, ew, hA, hB, nedges);
    zero_kernel<<<1, 256>>>(stats, 2 * D);
    colstats_kernel<<<592, D>>>(hB, nrows);
    bnfinal_kernel<<<1, D>>>(g0, be0, inv_n);

    // ---- layer 2 (BN+ReLU of layer-1 output fused into this GEMM's load) ----
    gemm_kernel<<<gemm_grid, 256>>>(hB, W1, b1, scale, shift, hA, nrows, 1);
    zero_kernel<<<1024, 256>>>(hB, nelem);
    spmm_kernel<<<spmm_blocks, 256>>>(row, col, ew, hA, hB, nedges);
    zero_kernel<<<1, 256>>>(stats, 2 * D);
    colstats_kernel<<<592, D>>>(hB, nrows);
    bnfinal_kernel<<<1, D>>>(g1, be1, inv_n);

    // ---- layer 3: out = spmm(relu(bn(h)) @ W2 + b2), no BN/act at the end ----
    gemm_kernel<<<gemm_grid, 256>>>(hB, W2, b2, scale, shift, hA, nrows, 1);
    zero_kernel<<<1024, 256>>>(out, nelem);
    spmm_kernel<<<spmm_blocks, 256>>>(row, col, ew, hA, out, nedges);
}